// round 7
// baseline (speedup 1.0000x reference)
#include <cuda_runtime.h>
#include <cstdint>

#define NQMAX 8192
#define DIM   256
#define NB    64
#define SCALE 0.0625f   /* 1/sqrt(256) exactly */

// ---------------- scratch (device globals: allocation-free) ----------------
__device__ float g_Q[NQMAX * DIM];
__device__ float g_K[NQMAX * DIM];
__device__ float g_V[NQMAX * DIM];
__device__ float g_O[NQMAX * DIM];
__device__ int   g_qseg[NB + 1];
__device__ int   g_kseg[NB + 1];

// ---------------- segment boundaries (lower_bound per batch) ---------------
__global__ void seg_kernel(const int* __restrict__ qb, const int* __restrict__ kb,
                           int n, int m) {
    int b = threadIdx.x;
    if (b <= NB) {
        int lo = 0, hi = n;
        while (lo < hi) { int mid = (lo + hi) >> 1; if (qb[mid] < b) lo = mid + 1; else hi = mid; }
        g_qseg[b] = lo;
        lo = 0; hi = m;
        while (lo < hi) { int mid = (lo + hi) >> 1; if (kb[mid] < b) lo = mid + 1; else hi = mid; }
        g_kseg[b] = lo;
    }
}

// ---------------- tf32 / mma helpers ---------------------------------------
__device__ __forceinline__ unsigned f2tf32(float x) {
    unsigned r;
    asm("cvt.rna.tf32.f32 %0, %1;" : "=r"(r) : "f"(x));
    return r;
}
__device__ __forceinline__ void split_tf32(float x, unsigned& hi, unsigned& lo) {
    hi = f2tf32(x);
    lo = f2tf32(x - __uint_as_float(hi));
}
__device__ __forceinline__ void mma_tf32(float* d, const unsigned* a, const unsigned* b) {
    asm volatile(
        "mma.sync.aligned.m16n8k8.row.col.f32.tf32.tf32.f32 "
        "{%0,%1,%2,%3}, {%4,%5,%6,%7}, {%8,%9}, {%0,%1,%2,%3};\n"
        : "+f"(d[0]), "+f"(d[1]), "+f"(d[2]), "+f"(d[3])
        : "r"(a[0]), "r"(a[1]), "r"(a[2]), "r"(a[3]), "r"(b[0]), "r"(b[1]));
}
__device__ __forceinline__ void cp16z(void* s, const void* g, bool p) {
    unsigned sa = (unsigned)__cvta_generic_to_shared(s);
    int sz = p ? 16 : 0;
    asm volatile("cp.async.cg.shared.global [%0], [%1], 16, %2;\n"
                 :: "r"(sa), "l"(g), "r"(sz));
}

// ---------------- GEMM: C[Mr,256] = A[Mr,256] @ W[256,256]^T + bias --------
// 3xTF32 on tensor cores. Store-time interleaved hi/lo split: smem holds
// (hi,lo) pairs, pitch 72 (frag LDS.64 conflict-free: bank-pair = 4*gid+tig).
// Register double-buffered LDG. Block tile 128x64, 8 warps, warp tile 32x32.
// If zero_ptr != nullptr, blockIdx.y == 0 is a zero-fill slice (dispatched
// FIRST so the 268MB DRAM writes overlap the whole GEMM phase).
#define GP   72                      /* floats per row: 32 k * (hi,lo) + pad */
#define GEMM_SMEM_F (192 * GP)       /* A 128 rows + W 64 rows = 55296 B */
#define NZB  192

extern __shared__ float sm_gemm[];

__global__ __launch_bounds__(256)
void gemm3_tf32(const float* __restrict__ A0, const float* __restrict__ A12,
                const float* __restrict__ W0, const float* __restrict__ b0,
                const float* __restrict__ W1, const float* __restrict__ b1,
                const float* __restrict__ W2, const float* __restrict__ b2,
                float* __restrict__ C0, float* __restrict__ C1, float* __restrict__ C2,
                float* __restrict__ zero_ptr, size_t zero_f4) {
    int t = threadIdx.x;
    bool has_zero = (zero_ptr != nullptr);

    if (has_zero && blockIdx.y == 0) {
        // zero-fill slice: 192 blocks grid-stride over the dense attn region
        size_t start = (size_t)(blockIdx.z * gridDim.x + blockIdx.x) * 256 + t;
        float4* p = (float4*)zero_ptr;
        float4 z4 = make_float4(0.f, 0.f, 0.f, 0.f);
        for (size_t i = start; i < zero_f4; i += (size_t)NZB * 256)
            p[i] = z4;
        return;
    }

    int z = blockIdx.z;
    const float* A    = (z == 0) ? A0 : A12;
    const float* W    = (z == 0) ? W0 : ((z == 1) ? W1 : W2);
    const float* bias = (z == 0) ? b0 : ((z == 1) ? b1 : b2);
    float*       C    = (z == 0) ? C0 : ((z == 1) ? C1 : C2);

    int w = t >> 5, lane = t & 31;
    int gid = lane >> 2, tig = lane & 3;
    int m0 = blockIdx.x * 128;
    int n0 = ((int)blockIdx.y - (has_zero ? 1 : 0)) * 64;
    int wm = (w >> 1) * 32;
    int wn = (w & 1) * 32;

    float* sA = sm_gemm;              // 128 rows x GP
    float* sW = sm_gemm + 128 * GP;   // 64 rows x GP

    // per-thread global-load coords (A: 4 float4, W: 2 float4 per chunk)
    int ra[4], ca[4], rw[2], cw[2];
    #pragma unroll
    for (int i = 0; i < 4; i++) { int f = t + i * 256; ra[i] = f >> 3; ca[i] = (f & 7) * 4; }
    #pragma unroll
    for (int i = 0; i < 2; i++) { int f = t + i * 256; rw[i] = f >> 3; cw[i] = (f & 7) * 4; }

    float acc[2][4][4] = {};
    float4 avA[4], avW[2];

    // prefetch chunk 0
    #pragma unroll
    for (int i = 0; i < 4; i++)
        avA[i] = *(const float4*)&A[(size_t)(m0 + ra[i]) * DIM + ca[i]];
    #pragma unroll
    for (int i = 0; i < 2; i++)
        avW[i] = *(const float4*)&W[(size_t)(n0 + rw[i]) * DIM + cw[i]];

    for (int kk = 0; kk < DIM; kk += 32) {
        // convert prefetched regs -> interleaved (hi,lo) smem
        #pragma unroll
        for (int i = 0; i < 4; i++) {
            float v[4] = {avA[i].x, avA[i].y, avA[i].z, avA[i].w};
            unsigned h[4], l[4];
            #pragma unroll
            for (int e = 0; e < 4; e++) split_tf32(v[e], h[e], l[e]);
            float* d = &sA[ra[i] * GP + 2 * ca[i]];
            *(float4*)d = make_float4(__uint_as_float(h[0]), __uint_as_float(l[0]),
                                      __uint_as_float(h[1]), __uint_as_float(l[1]));
            *(float4*)(d + 4) = make_float4(__uint_as_float(h[2]), __uint_as_float(l[2]),
                                            __uint_as_float(h[3]), __uint_as_float(l[3]));
        }
        #pragma unroll
        for (int i = 0; i < 2; i++) {
            float v[4] = {avW[i].x, avW[i].y, avW[i].z, avW[i].w};
            unsigned h[4], l[4];
            #pragma unroll
            for (int e = 0; e < 4; e++) split_tf32(v[e], h[e], l[e]);
            float* d = &sW[rw[i] * GP + 2 * cw[i]];
            *(float4*)d = make_float4(__uint_as_float(h[0]), __uint_as_float(l[0]),
                                      __uint_as_float(h[1]), __uint_as_float(l[1]));
            *(float4*)(d + 4) = make_float4(__uint_as_float(h[2]), __uint_as_float(l[2]),
                                            __uint_as_float(h[3]), __uint_as_float(l[3]));
        }
        __syncthreads();

        // prefetch next chunk (LDG latency hides behind the MMA phase)
        if (kk + 32 < DIM) {
            #pragma unroll
            for (int i = 0; i < 4; i++)
                avA[i] = *(const float4*)&A[(size_t)(m0 + ra[i]) * DIM + kk + 32 + ca[i]];
            #pragma unroll
            for (int i = 0; i < 2; i++)
                avW[i] = *(const float4*)&W[(size_t)(n0 + rw[i]) * DIM + kk + 32 + cw[i]];
        }

        // MMA phase: pure LDS.64 + mma
        #pragma unroll
        for (int ks = 0; ks < 32; ks += 8) {
            int c = ks + tig;
            unsigned ah[2][4], al[2][4], bh[4][2], bl[4][2];
            #pragma unroll
            for (int i = 0; i < 2; i++) {
                int mr = wm + i * 16 + gid;
                float2 p0 = *(const float2*)&sA[mr * GP + 2 * c];
                float2 p1 = *(const float2*)&sA[(mr + 8) * GP + 2 * c];
                float2 p2 = *(const float2*)&sA[mr * GP + 2 * (c + 4)];
                float2 p3 = *(const float2*)&sA[(mr + 8) * GP + 2 * (c + 4)];
                ah[i][0] = __float_as_uint(p0.x); al[i][0] = __float_as_uint(p0.y);
                ah[i][1] = __float_as_uint(p1.x); al[i][1] = __float_as_uint(p1.y);
                ah[i][2] = __float_as_uint(p2.x); al[i][2] = __float_as_uint(p2.y);
                ah[i][3] = __float_as_uint(p3.x); al[i][3] = __float_as_uint(p3.y);
            }
            #pragma unroll
            for (int j = 0; j < 4; j++) {
                int nr = wn + j * 8 + gid;
                float2 q0 = *(const float2*)&sW[nr * GP + 2 * c];
                float2 q1 = *(const float2*)&sW[nr * GP + 2 * (c + 4)];
                bh[j][0] = __float_as_uint(q0.x); bl[j][0] = __float_as_uint(q0.y);
                bh[j][1] = __float_as_uint(q1.x); bl[j][1] = __float_as_uint(q1.y);
            }
            #pragma unroll
            for (int i = 0; i < 2; i++)
                #pragma unroll
                for (int j = 0; j < 4; j++) {
                    mma_tf32(acc[i][j], ah[i], bh[j]);
                    mma_tf32(acc[i][j], ah[i], bl[j]);
                    mma_tf32(acc[i][j], al[i], bh[j]);
                }
        }
        __syncthreads();
    }

    #pragma unroll
    for (int i = 0; i < 2; i++) {
        #pragma unroll
        for (int j = 0; j < 4; j++) {
            int n = n0 + wn + j * 8 + tig * 2;
            float bb0 = __ldg(&bias[n]), bb1 = __ldg(&bias[n + 1]);
            int m = m0 + wm + i * 16 + gid;
            *(float2*)&C[(size_t)m * DIM + n] =
                make_float2(acc[i][j][0] + bb0, acc[i][j][1] + bb1);
            *(float2*)&C[(size_t)(m + 8) * DIM + n] =
                make_float2(acc[i][j][2] + bb0, acc[i][j][3] + bb1);
        }
    }
}

// ---------------- tensor-core block-diagonal attention (unchanged R6) -------
#define AP 260
#define VP 264
#define PP 36
#define ATTN_SMEM_F (32 * AP * 2 + 32 * VP + 32 * PP + 32)

extern __shared__ float sm_attn[];

__global__ __launch_bounds__(256)
void attn_mma(const float* __restrict__ Q, const float* __restrict__ K,
              const float* __restrict__ V, float* __restrict__ attn,
              float* __restrict__ O, int Mtot) {
    int b  = blockIdx.x;
    int qs = g_qseg[b], qe = g_qseg[b + 1];
    int row0 = qs + blockIdx.y * 32;
    if (row0 >= qe) return;
    int rows = min(32, qe - row0);
    int ks = g_kseg[b], ke = g_kseg[b + 1];
    int nk = ke - ks;

    int t = threadIdx.x;
    int w = t >> 5, lane = t & 31;
    int gid = lane >> 2, tig = lane & 3;

    float* Qs = sm_attn;
    float* Ks = Qs + 32 * AP;
    float* Vs = Ks + 32 * AP;
    float* Ps = Vs + 32 * VP;
    float* rowsum = Ps + 32 * PP;

    if (nk == 0) {
        for (int i = t; i < rows * DIM; i += 256)
            O[(size_t)row0 * DIM + i] = 0.f;
        return;
    }

    for (int i = t; i < 32 * 64; i += 256) {
        int r = i >> 6, c4 = i & 63;
        cp16z(&Qs[r * AP + c4 * 4], &Q[(size_t)(row0 + r) * DIM + c4 * 4], r < rows);
    }
    asm volatile("cp.async.commit_group;\n");
    if (t < 32) rowsum[t] = 0.f;

    int mh  = w & 1;
    int wn0 = (w >> 1) * 8;

    float o_acc[2][4][4] = {};

    int ntiles = (nk + 31) >> 5;
    for (int kt = 0; kt < ntiles; kt++) {
        int kbase = kt << 5;
        __syncthreads();
        for (int i = t; i < 32 * 64; i += 256) {
            int r = i >> 6, c4 = i & 63;
            bool p = kbase + r < nk;
            cp16z(&Ks[r * AP + c4 * 4], &K[(size_t)(ks + kbase + r) * DIM + c4 * 4], p);
            cp16z(&Vs[r * VP + c4 * 4], &V[(size_t)(ks + kbase + r) * DIM + c4 * 4], p);
        }
        asm volatile("cp.async.commit_group;\n");
        asm volatile("cp.async.wait_group 0;\n");
        __syncthreads();

        float sacc[4] = {0.f, 0.f, 0.f, 0.f};
        #pragma unroll
        for (int kk = 0; kk < DIM; kk += 8) {
            unsigned ah[4], al[4], bh[2], bl[2];
            int c = kk + tig;
            int mr = mh * 16 + gid;
            split_tf32(Qs[mr * AP + c],           ah[0], al[0]);
            split_tf32(Qs[(mr + 8) * AP + c],     ah[1], al[1]);
            split_tf32(Qs[mr * AP + c + 4],       ah[2], al[2]);
            split_tf32(Qs[(mr + 8) * AP + c + 4], ah[3], al[3]);
            int nr = wn0 + gid;
            split_tf32(Ks[nr * AP + c],     bh[0], bl[0]);
            split_tf32(Ks[nr * AP + c + 4], bh[1], bl[1]);
            mma_tf32(sacc, ah, bh);
            mma_tf32(sacc, ah, bl);
            mma_tf32(sacc, al, bh);
        }
        int kn = kbase + wn0 + 2 * tig;
        float e0 = (kn     < nk) ? __expf(sacc[0] * SCALE) : 0.f;
        float e1 = (kn + 1 < nk) ? __expf(sacc[1] * SCALE) : 0.f;
        float e2 = (kn     < nk) ? __expf(sacc[2] * SCALE) : 0.f;
        float e3 = (kn + 1 < nk) ? __expf(sacc[3] * SCALE) : 0.f;
        int pr = mh * 16 + gid;
        Ps[pr * PP + wn0 + 2 * tig]           = e0;
        Ps[pr * PP + wn0 + 2 * tig + 1]       = e1;
        Ps[(pr + 8) * PP + wn0 + 2 * tig]     = e2;
        Ps[(pr + 8) * PP + wn0 + 2 * tig + 1] = e3;
        __syncthreads();

        #pragma unroll
        for (int i = 0; i < 4; i++) {
            int r = w + i * 8;
            float e = Ps[r * PP + lane];
            float s = e;
            #pragma unroll
            for (int off = 16; off; off >>= 1) s += __shfl_xor_sync(0xFFFFFFFFu, s, off);
            if (lane == 0) rowsum[r] += s;
            if (r < rows && kbase + lane < nk)
                attn[(size_t)(row0 + r) * Mtot + ks + kbase + lane] = e;
        }

        #pragma unroll
        for (int kk = 0; kk < 32; kk += 8) {
            unsigned pah[2][4], pal[2][4];
            int c = kk + tig;
            #pragma unroll
            for (int i = 0; i < 2; i++) {
                int mr = i * 16 + gid;
                split_tf32(Ps[mr * PP + c],           pah[i][0], pal[i][0]);
                split_tf32(Ps[(mr + 8) * PP + c],     pah[i][1], pal[i][1]);
                split_tf32(Ps[mr * PP + c + 4],       pah[i][2], pal[i][2]);
                split_tf32(Ps[(mr + 8) * PP + c + 4], pah[i][3], pal[i][3]);
            }
            #pragma unroll
            for (int j = 0; j < 4; j++) {
                int n = w * 32 + 8 * j + gid;
                unsigned vbh[2], vbl[2];
                split_tf32(Vs[c * VP + n],       vbh[0], vbl[0]);
                split_tf32(Vs[(c + 4) * VP + n], vbh[1], vbl[1]);
                #pragma unroll
                for (int i = 0; i < 2; i++) {
                    mma_tf32(o_acc[i][j], pah[i], vbh);
                    mma_tf32(o_acc[i][j], pah[i], vbl);
                    mma_tf32(o_acc[i][j], pal[i], vbh);
                }
            }
        }
    }
    __syncthreads();
    if (t < 32) rowsum[t] = (rowsum[t] > 0.f) ? (1.f / rowsum[t]) : 0.f;
    __syncthreads();

    #pragma unroll
    for (int i = 0; i < 4; i++) {
        int r = w + i * 8;
        if (r < rows) {
            float inv = rowsum[r];
            size_t base = (size_t)(row0 + r) * Mtot + ks;
            for (int j = lane; j < nk; j += 32) attn[base + j] *= inv;
        }
    }
    #pragma unroll
    for (int i = 0; i < 2; i++) {
        int r = i * 16 + gid;
        if (r < rows) {
            float inv = rowsum[r];
            #pragma unroll
            for (int j = 0; j < 4; j++) {
                int n = w * 32 + 8 * j + 2 * tig;
                *(float2*)&O[(size_t)(row0 + r) * DIM + n] =
                    make_float2(o_acc[i][j][0] * inv, o_acc[i][j][1] * inv);
            }
        }
        int r8 = r + 8;
        if (r8 < rows) {
            float inv = rowsum[r8];
            #pragma unroll
            for (int j = 0; j < 4; j++) {
                int n = w * 32 + 8 * j + 2 * tig;
                *(float2*)&O[(size_t)(row0 + r8) * DIM + n] =
                    make_float2(o_acc[i][j][2] * inv, o_acc[i][j][3] * inv);
            }
        }
    }
}

// ---------------- launch (single stream, no events) -------------------------
extern "C" void kernel_launch(void* const* d_in, const int* in_sizes, int n_in,
                              void* d_out, int out_size) {
    const float* q_feat = (const float*)d_in[0];
    const float* k_feat = (const float*)d_in[1];
    const int*   q_batch = (const int*)d_in[2];
    const int*   k_batch = (const int*)d_in[3];
    const float* Wq = (const float*)d_in[4];
    const float* bq = (const float*)d_in[5];
    const float* Wk = (const float*)d_in[6];
    const float* bk = (const float*)d_in[7];
    const float* Wv = (const float*)d_in[8];
    const float* bv = (const float*)d_in[9];
    const float* Wo = (const float*)d_in[10];
    const float* bo = (const float*)d_in[11];

    int n = in_sizes[0] / DIM;
    int m = in_sizes[1] / DIM;

    float* out      = (float*)d_out;
    float* attended = out;                        // [n, DIM]
    float* attn     = out + (size_t)n * DIM;      // [n, m]

    float *Qd, *Kd, *Vd, *Od;
    cudaGetSymbolAddress((void**)&Qd, g_Q);
    cudaGetSymbolAddress((void**)&Kd, g_K);
    cudaGetSymbolAddress((void**)&Vd, g_V);
    cudaGetSymbolAddress((void**)&Od, g_O);

    const size_t attn_smem = ATTN_SMEM_F * sizeof(float);
    const size_t gemm_smem = GEMM_SMEM_F * sizeof(float);
    cudaFuncSetAttribute(attn_mma, cudaFuncAttributeMaxDynamicSharedMemorySize,
                         (int)attn_smem);
    cudaFuncSetAttribute(gemm3_tf32, cudaFuncAttributeMaxDynamicSharedMemorySize,
                         (int)gemm_smem);

    size_t attn_f4 = (size_t)n * m / 4;

    // 1. segments
    seg_kernel<<<1, 128>>>(q_batch, k_batch, n, m);
    // 2. fused QKV projection + attn zero-fill (y==0 slice dispatches first)
    gemm3_tf32<<<dim3(n / 128, 5, 3), 256, gemm_smem>>>(
        q_feat, k_feat, Wq, bq, Wk, bk, Wv, bv, Qd, Kd, Vd, attn, attn_f4);
    // 3. tensor-core block-diagonal attention
    attn_mma<<<dim3(NB, 32), 256, attn_smem>>>(Qd, Kd, Vd, attn, Od, m);
    // 4. output projection (no zero slice)
    gemm3_tf32<<<dim3(n / 128, 4, 1), 256, gemm_smem>>>(
        Od, Od, Wo, bo, Wo, bo, Wo, bo, attended, attended, attended,
        nullptr, 0);
}

// round 8
// speedup vs baseline: 1.1625x; 1.1625x over previous
#include <cuda_runtime.h>
#include <cstdint>

#define NQMAX 8192
#define DIM   256
#define NB    64
#define SCALE 0.0625f   /* 1/sqrt(256) exactly */

// ---------------- scratch (device globals: allocation-free) ----------------
__device__ float g_Q[NQMAX * DIM];
__device__ float g_K[NQMAX * DIM];
__device__ float g_V[NQMAX * DIM];
__device__ float g_O[NQMAX * DIM];
__device__ int   g_qseg[NB + 1];
__device__ int   g_kseg[NB + 1];

// ---------------- tf32 / mma helpers ---------------------------------------
__device__ __forceinline__ unsigned f2tf32(float x) {
    unsigned r;
    asm("cvt.rna.tf32.f32 %0, %1;" : "=r"(r) : "f"(x));
    return r;
}
__device__ __forceinline__ void split_tf32(float x, unsigned& hi, unsigned& lo) {
    hi = f2tf32(x);
    lo = f2tf32(x - __uint_as_float(hi));
}
__device__ __forceinline__ void mma_tf32(float* d, const unsigned* a, const unsigned* b) {
    asm volatile(
        "mma.sync.aligned.m16n8k8.row.col.f32.tf32.tf32.f32 "
        "{%0,%1,%2,%3}, {%4,%5,%6,%7}, {%8,%9}, {%0,%1,%2,%3};\n"
        : "+f"(d[0]), "+f"(d[1]), "+f"(d[2]), "+f"(d[3])
        : "r"(a[0]), "r"(a[1]), "r"(a[2]), "r"(a[3]), "r"(b[0]), "r"(b[1]));
}
__device__ __forceinline__ void cp16z(void* s, const void* g, bool p) {
    unsigned sa = (unsigned)__cvta_generic_to_shared(s);
    int sz = p ? 16 : 0;
    asm volatile("cp.async.cg.shared.global [%0], [%1], 16, %2;\n"
                 :: "r"(sa), "l"(g), "r"(sz));
}

// ---------------- GEMM: C[Mr,256] = A[Mr,256] @ W[256,256]^T + bias --------
// R3 body (measured best: 29.1us): 3xTF32 split at smem-store time into
// separate hi/lo arrays, pitch 36 (frag bank = 4r+c, conflict-free), no
// pipeline. Wrapped with z-fusion + head-dispatched zero-fill slice + seg.
#define GP 36
#define SA_HI 0
#define SA_LO (128 * GP)
#define SW_HI (2 * 128 * GP)
#define SW_LO (2 * 128 * GP + 64 * GP)
#define GEMM_SMEM_U32 (2 * 128 * GP + 2 * 64 * GP)
#define NZB  192

extern __shared__ unsigned sm_gemm[];

__global__ __launch_bounds__(256)
void gemm3_tf32(const float* __restrict__ A0, const float* __restrict__ A12,
                const float* __restrict__ W0, const float* __restrict__ b0,
                const float* __restrict__ W1, const float* __restrict__ b1,
                const float* __restrict__ W2, const float* __restrict__ b2,
                float* __restrict__ C0, float* __restrict__ C1, float* __restrict__ C2,
                float* __restrict__ zero_ptr, size_t zero_f4,
                const int* __restrict__ qb, const int* __restrict__ kb,
                int nq, int mk) {
    int t = threadIdx.x;
    bool has_zero = (zero_ptr != nullptr);

    if (has_zero && blockIdx.y == 0) {
        // one block also computes segment boundaries for the attn kernel
        if (blockIdx.x == 0 && blockIdx.z == 0 && t <= NB) {
            int b = t;
            int lo = 0, hi = nq;
            while (lo < hi) { int mid = (lo + hi) >> 1; if (qb[mid] < b) lo = mid + 1; else hi = mid; }
            g_qseg[b] = lo;
            lo = 0; hi = mk;
            while (lo < hi) { int mid = (lo + hi) >> 1; if (kb[mid] < b) lo = mid + 1; else hi = mid; }
            g_kseg[b] = lo;
        }
        // zero-fill slice: 192 blocks grid-stride over the dense attn region,
        // dispatched at the head of each z-slice -> overlaps the GEMM phase
        size_t start = (size_t)(blockIdx.z * gridDim.x + blockIdx.x) * 256 + t;
        float4* p = (float4*)zero_ptr;
        float4 z4 = make_float4(0.f, 0.f, 0.f, 0.f);
        for (size_t i = start; i < zero_f4; i += (size_t)NZB * 256)
            p[i] = z4;
        return;
    }

    int z = blockIdx.z;
    const float* A    = (z == 0) ? A0 : A12;
    const float* W    = (z == 0) ? W0 : ((z == 1) ? W1 : W2);
    const float* bias = (z == 0) ? b0 : ((z == 1) ? b1 : b2);
    float*       C    = (z == 0) ? C0 : ((z == 1) ? C1 : C2);

    int w = t >> 5, lane = t & 31;
    int gid = lane >> 2, tig = lane & 3;
    int m0 = blockIdx.x * 128;
    int n0 = ((int)blockIdx.y - (has_zero ? 1 : 0)) * 64;
    int wm = (w >> 1) * 32;
    int wn = (w & 1) * 32;

    unsigned* sAhi = sm_gemm + SA_HI;
    unsigned* sAlo = sm_gemm + SA_LO;
    unsigned* sWhi = sm_gemm + SW_HI;
    unsigned* sWlo = sm_gemm + SW_LO;

    float acc[2][4][4] = {};

    for (int kk = 0; kk < DIM; kk += 32) {
        __syncthreads();
        // load A tile 128x32 (4 float4/thread), split at store
        #pragma unroll
        for (int i = 0; i < 4; i++) {
            int f = t + i * 256;
            int r = f >> 3, c4 = f & 7;
            float4 av = *(const float4*)&A[(size_t)(m0 + r) * DIM + kk + c4 * 4];
            float vv[4] = {av.x, av.y, av.z, av.w};
            #pragma unroll
            for (int e = 0; e < 4; e++) {
                unsigned hb = f2tf32(vv[e]);
                float hf = __uint_as_float(hb);
                sAhi[r * GP + c4 * 4 + e] = hb;
                sAlo[r * GP + c4 * 4 + e] = f2tf32(vv[e] - hf);
            }
        }
        // load W tile 64x32 (2 float4/thread)
        #pragma unroll
        for (int i = 0; i < 2; i++) {
            int f = t + i * 256;
            int r = f >> 3, c4 = f & 7;
            float4 wv = *(const float4*)&W[(size_t)(n0 + r) * DIM + kk + c4 * 4];
            float vv[4] = {wv.x, wv.y, wv.z, wv.w};
            #pragma unroll
            for (int e = 0; e < 4; e++) {
                unsigned hb = f2tf32(vv[e]);
                float hf = __uint_as_float(hb);
                sWhi[r * GP + c4 * 4 + e] = hb;
                sWlo[r * GP + c4 * 4 + e] = f2tf32(vv[e] - hf);
            }
        }
        __syncthreads();

        #pragma unroll
        for (int ks = 0; ks < 32; ks += 8) {
            unsigned ah[2][4], al[2][4], bh[4][2], bl[4][2];
            #pragma unroll
            for (int i = 0; i < 2; i++) {
                int mr = wm + i * 16 + gid;
                int c  = ks + tig;
                ah[i][0] = sAhi[mr * GP + c];
                ah[i][1] = sAhi[(mr + 8) * GP + c];
                ah[i][2] = sAhi[mr * GP + c + 4];
                ah[i][3] = sAhi[(mr + 8) * GP + c + 4];
                al[i][0] = sAlo[mr * GP + c];
                al[i][1] = sAlo[(mr + 8) * GP + c];
                al[i][2] = sAlo[mr * GP + c + 4];
                al[i][3] = sAlo[(mr + 8) * GP + c + 4];
            }
            #pragma unroll
            for (int j = 0; j < 4; j++) {
                int nr = wn + j * 8 + gid;
                int c  = ks + tig;
                bh[j][0] = sWhi[nr * GP + c];
                bh[j][1] = sWhi[nr * GP + c + 4];
                bl[j][0] = sWlo[nr * GP + c];
                bl[j][1] = sWlo[nr * GP + c + 4];
            }
            #pragma unroll
            for (int i = 0; i < 2; i++)
                #pragma unroll
                for (int j = 0; j < 4; j++) {
                    mma_tf32(acc[i][j], ah[i], bh[j]);
                    mma_tf32(acc[i][j], ah[i], bl[j]);
                    mma_tf32(acc[i][j], al[i], bh[j]);
                }
        }
    }

    #pragma unroll
    for (int i = 0; i < 2; i++) {
        #pragma unroll
        for (int j = 0; j < 4; j++) {
            int n = n0 + wn + j * 8 + tig * 2;
            float bb0 = __ldg(&bias[n]), bb1 = __ldg(&bias[n + 1]);
            int m = m0 + wm + i * 16 + gid;
            *(float2*)&C[(size_t)m * DIM + n] =
                make_float2(acc[i][j][0] + bb0, acc[i][j][1] + bb1);
            *(float2*)&C[(size_t)(m + 8) * DIM + n] =
                make_float2(acc[i][j][2] + bb0, acc[i][j][3] + bb1);
        }
    }
}

// ---------------- tensor-core block-diagonal attention (unchanged R6) -------
#define AP 260
#define VP 264
#define PP 36
#define ATTN_SMEM_F (32 * AP * 2 + 32 * VP + 32 * PP + 32)

extern __shared__ float sm_attn[];

__global__ __launch_bounds__(256)
void attn_mma(const float* __restrict__ Q, const float* __restrict__ K,
              const float* __restrict__ V, float* __restrict__ attn,
              float* __restrict__ O, int Mtot) {
    int b  = blockIdx.x;
    int qs = g_qseg[b], qe = g_qseg[b + 1];
    int row0 = qs + blockIdx.y * 32;
    if (row0 >= qe) return;
    int rows = min(32, qe - row0);
    int ks = g_kseg[b], ke = g_kseg[b + 1];
    int nk = ke - ks;

    int t = threadIdx.x;
    int w = t >> 5, lane = t & 31;
    int gid = lane >> 2, tig = lane & 3;

    float* Qs = sm_attn;
    float* Ks = Qs + 32 * AP;
    float* Vs = Ks + 32 * AP;
    float* Ps = Vs + 32 * VP;
    float* rowsum = Ps + 32 * PP;

    if (nk == 0) {
        for (int i = t; i < rows * DIM; i += 256)
            O[(size_t)row0 * DIM + i] = 0.f;
        return;
    }

    for (int i = t; i < 32 * 64; i += 256) {
        int r = i >> 6, c4 = i & 63;
        cp16z(&Qs[r * AP + c4 * 4], &Q[(size_t)(row0 + r) * DIM + c4 * 4], r < rows);
    }
    asm volatile("cp.async.commit_group;\n");
    if (t < 32) rowsum[t] = 0.f;

    int mh  = w & 1;
    int wn0 = (w >> 1) * 8;

    float o_acc[2][4][4] = {};

    int ntiles = (nk + 31) >> 5;
    for (int kt = 0; kt < ntiles; kt++) {
        int kbase = kt << 5;
        __syncthreads();
        for (int i = t; i < 32 * 64; i += 256) {
            int r = i >> 6, c4 = i & 63;
            bool p = kbase + r < nk;
            cp16z(&Ks[r * AP + c4 * 4], &K[(size_t)(ks + kbase + r) * DIM + c4 * 4], p);
            cp16z(&Vs[r * VP + c4 * 4], &V[(size_t)(ks + kbase + r) * DIM + c4 * 4], p);
        }
        asm volatile("cp.async.commit_group;\n");
        asm volatile("cp.async.wait_group 0;\n");
        __syncthreads();

        float sacc[4] = {0.f, 0.f, 0.f, 0.f};
        #pragma unroll
        for (int kk = 0; kk < DIM; kk += 8) {
            unsigned ah[4], al[4], bh[2], bl[2];
            int c = kk + tig;
            int mr = mh * 16 + gid;
            split_tf32(Qs[mr * AP + c],           ah[0], al[0]);
            split_tf32(Qs[(mr + 8) * AP + c],     ah[1], al[1]);
            split_tf32(Qs[mr * AP + c + 4],       ah[2], al[2]);
            split_tf32(Qs[(mr + 8) * AP + c + 4], ah[3], al[3]);
            int nr = wn0 + gid;
            split_tf32(Ks[nr * AP + c],     bh[0], bl[0]);
            split_tf32(Ks[nr * AP + c + 4], bh[1], bl[1]);
            mma_tf32(sacc, ah, bh);
            mma_tf32(sacc, ah, bl);
            mma_tf32(sacc, al, bh);
        }
        int kn = kbase + wn0 + 2 * tig;
        float e0 = (kn     < nk) ? __expf(sacc[0] * SCALE) : 0.f;
        float e1 = (kn + 1 < nk) ? __expf(sacc[1] * SCALE) : 0.f;
        float e2 = (kn     < nk) ? __expf(sacc[2] * SCALE) : 0.f;
        float e3 = (kn + 1 < nk) ? __expf(sacc[3] * SCALE) : 0.f;
        int pr = mh * 16 + gid;
        Ps[pr * PP + wn0 + 2 * tig]           = e0;
        Ps[pr * PP + wn0 + 2 * tig + 1]       = e1;
        Ps[(pr + 8) * PP + wn0 + 2 * tig]     = e2;
        Ps[(pr + 8) * PP + wn0 + 2 * tig + 1] = e3;
        __syncthreads();

        #pragma unroll
        for (int i = 0; i < 4; i++) {
            int r = w + i * 8;
            float e = Ps[r * PP + lane];
            float s = e;
            #pragma unroll
            for (int off = 16; off; off >>= 1) s += __shfl_xor_sync(0xFFFFFFFFu, s, off);
            if (lane == 0) rowsum[r] += s;
            if (r < rows && kbase + lane < nk)
                attn[(size_t)(row0 + r) * Mtot + ks + kbase + lane] = e;
        }

        #pragma unroll
        for (int kk = 0; kk < 32; kk += 8) {
            unsigned pah[2][4], pal[2][4];
            int c = kk + tig;
            #pragma unroll
            for (int i = 0; i < 2; i++) {
                int mr = i * 16 + gid;
                split_tf32(Ps[mr * PP + c],           pah[i][0], pal[i][0]);
                split_tf32(Ps[(mr + 8) * PP + c],     pah[i][1], pal[i][1]);
                split_tf32(Ps[mr * PP + c + 4],       pah[i][2], pal[i][2]);
                split_tf32(Ps[(mr + 8) * PP + c + 4], pah[i][3], pal[i][3]);
            }
            #pragma unroll
            for (int j = 0; j < 4; j++) {
                int n = w * 32 + 8 * j + gid;
                unsigned vbh[2], vbl[2];
                split_tf32(Vs[c * VP + n],       vbh[0], vbl[0]);
                split_tf32(Vs[(c + 4) * VP + n], vbh[1], vbl[1]);
                #pragma unroll
                for (int i = 0; i < 2; i++) {
                    mma_tf32(o_acc[i][j], pah[i], vbh);
                    mma_tf32(o_acc[i][j], pah[i], vbl);
                    mma_tf32(o_acc[i][j], pal[i], vbh);
                }
            }
        }
    }
    __syncthreads();
    if (t < 32) rowsum[t] = (rowsum[t] > 0.f) ? (1.f / rowsum[t]) : 0.f;
    __syncthreads();

    #pragma unroll
    for (int i = 0; i < 4; i++) {
        int r = w + i * 8;
        if (r < rows) {
            float inv = rowsum[r];
            size_t base = (size_t)(row0 + r) * Mtot + ks;
            for (int j = lane; j < nk; j += 32) attn[base + j] *= inv;
        }
    }
    #pragma unroll
    for (int i = 0; i < 2; i++) {
        int r = i * 16 + gid;
        if (r < rows) {
            float inv = rowsum[r];
            #pragma unroll
            for (int j = 0; j < 4; j++) {
                int n = w * 32 + 8 * j + 2 * tig;
                *(float2*)&O[(size_t)(row0 + r) * DIM + n] =
                    make_float2(o_acc[i][j][0] * inv, o_acc[i][j][1] * inv);
            }
        }
        int r8 = r + 8;
        if (r8 < rows) {
            float inv = rowsum[r8];
            #pragma unroll
            for (int j = 0; j < 4; j++) {
                int n = w * 32 + 8 * j + 2 * tig;
                *(float2*)&O[(size_t)(row0 + r8) * DIM + n] =
                    make_float2(o_acc[i][j][2] * inv, o_acc[i][j][3] * inv);
            }
        }
    }
}

// ---------------- launch (single stream, no events) -------------------------
extern "C" void kernel_launch(void* const* d_in, const int* in_sizes, int n_in,
                              void* d_out, int out_size) {
    const float* q_feat = (const float*)d_in[0];
    const float* k_feat = (const float*)d_in[1];
    const int*   q_batch = (const int*)d_in[2];
    const int*   k_batch = (const int*)d_in[3];
    const float* Wq = (const float*)d_in[4];
    const float* bq = (const float*)d_in[5];
    const float* Wk = (const float*)d_in[6];
    const float* bk = (const float*)d_in[7];
    const float* Wv = (const float*)d_in[8];
    const float* bv = (const float*)d_in[9];
    const float* Wo = (const float*)d_in[10];
    const float* bo = (const float*)d_in[11];

    int n = in_sizes[0] / DIM;
    int m = in_sizes[1] / DIM;

    float* out      = (float*)d_out;
    float* attended = out;                        // [n, DIM]
    float* attn     = out + (size_t)n * DIM;      // [n, m]

    float *Qd, *Kd, *Vd, *Od;
    cudaGetSymbolAddress((void**)&Qd, g_Q);
    cudaGetSymbolAddress((void**)&Kd, g_K);
    cudaGetSymbolAddress((void**)&Vd, g_V);
    cudaGetSymbolAddress((void**)&Od, g_O);

    const size_t attn_smem = ATTN_SMEM_F * sizeof(float);
    const size_t gemm_smem = GEMM_SMEM_U32 * sizeof(unsigned);
    cudaFuncSetAttribute(attn_mma, cudaFuncAttributeMaxDynamicSharedMemorySize,
                         (int)attn_smem);
    cudaFuncSetAttribute(gemm3_tf32, cudaFuncAttributeMaxDynamicSharedMemorySize,
                         (int)gemm_smem);

    size_t attn_f4 = (size_t)n * m / 4;

    // 1. fused QKV projection + attn zero-fill + segment boundaries
    //    (y==0 slice dispatches first in each z-slice: zero overlaps GEMM)
    gemm3_tf32<<<dim3(n / 128, 5, 3), 256, gemm_smem>>>(
        q_feat, k_feat, Wq, bq, Wk, bk, Wv, bv, Qd, Kd, Vd,
        attn, attn_f4, q_batch, k_batch, n, m);
    // 2. tensor-core block-diagonal attention
    attn_mma<<<dim3(NB, 32), 256, attn_smem>>>(Qd, Kd, Vd, attn, Od, m);
    // 3. output projection (no zero slice)
    gemm3_tf32<<<dim3(n / 128, 4, 1), 256, gemm_smem>>>(
        Od, Od, Wo, bo, Wo, bo, Wo, bo, attended, attended, attended,
        nullptr, 0, nullptr, nullptr, 0, 0);
}

// round 10
// speedup vs baseline: 1.1750x; 1.0107x over previous
#include <cuda_runtime.h>
#include <cstdint>

#define NQMAX 8192
#define DIM   256
#define NB    64
#define SCALE 0.0625f   /* 1/sqrt(256) exactly */

// ---------------- scratch (device globals: allocation-free) ----------------
__device__ float g_Q[NQMAX * DIM];
__device__ float g_K[NQMAX * DIM];
__device__ float g_V[NQMAX * DIM];
__device__ float g_O[NQMAX * DIM];
__device__ int   g_qseg[NB + 1];
__device__ int   g_kseg[NB + 1];

// ---------------- tf32 / mma helpers ---------------------------------------
__device__ __forceinline__ unsigned f2tf32(float x) {
    unsigned r;
    asm("cvt.rna.tf32.f32 %0, %1;" : "=r"(r) : "f"(x));
    return r;
}
__device__ __forceinline__ void split_tf32(float x, unsigned& hi, unsigned& lo) {
    hi = f2tf32(x);
    lo = f2tf32(x - __uint_as_float(hi));
}
__device__ __forceinline__ void mma_tf32(float* d, const unsigned* a, const unsigned* b) {
    asm volatile(
        "mma.sync.aligned.m16n8k8.row.col.f32.tf32.tf32.f32 "
        "{%0,%1,%2,%3}, {%4,%5,%6,%7}, {%8,%9}, {%0,%1,%2,%3};\n"
        : "+f"(d[0]), "+f"(d[1]), "+f"(d[2]), "+f"(d[3])
        : "r"(a[0]), "r"(a[1]), "r"(a[2]), "r"(a[3]), "r"(b[0]), "r"(b[1]));
}
__device__ __forceinline__ void cp16z(void* s, const void* g, bool p) {
    unsigned sa = (unsigned)__cvta_generic_to_shared(s);
    int sz = p ? 16 : 0;
    asm volatile("cp.async.cg.shared.global [%0], [%1], 16, %2;\n"
                 :: "r"(sa), "l"(g), "r"(sz));
}

// ---------------- GEMM: C[Mr,256] = A[Mr,256] @ W[256,256]^T + bias --------
// R3 body (measured best): 3xTF32 split at smem-store time into separate
// hi/lo arrays, pitch 36 (frag bank = 4r+c, conflict-free), no pipeline.
// __launch_bounds__(256,3) caps regs ~85 -> 3 CTAs/SM (R8 hit 96 regs -> 2).
// Wrapped with z-fusion + head-dispatched zero-fill slice + fused seg.
#define GP 36
#define SA_HI 0
#define SA_LO (128 * GP)
#define SW_HI (2 * 128 * GP)
#define SW_LO (2 * 128 * GP + 64 * GP)
#define GEMM_SMEM_U32 (2 * 128 * GP + 2 * 64 * GP)
#define NZB  192

extern __shared__ unsigned sm_gemm[];

__global__ __launch_bounds__(256, 3)
void gemm3_tf32(const float* __restrict__ A0, const float* __restrict__ A12,
                const float* __restrict__ W0, const float* __restrict__ b0,
                const float* __restrict__ W1, const float* __restrict__ b1,
                const float* __restrict__ W2, const float* __restrict__ b2,
                float* __restrict__ C0, float* __restrict__ C1, float* __restrict__ C2,
                float* __restrict__ zero_ptr, size_t zero_f4,
                const int* __restrict__ qb, const int* __restrict__ kb,
                int nq, int mk) {
    int t = threadIdx.x;
    bool has_zero = (zero_ptr != nullptr);

    if (has_zero && blockIdx.y == 0) {
        // one block also computes segment boundaries for the attn kernel
        if (blockIdx.x == 0 && blockIdx.z == 0 && t <= NB) {
            int b = t;
            int lo = 0, hi = nq;
            while (lo < hi) { int mid = (lo + hi) >> 1; if (qb[mid] < b) lo = mid + 1; else hi = mid; }
            g_qseg[b] = lo;
            lo = 0; hi = mk;
            while (lo < hi) { int mid = (lo + hi) >> 1; if (kb[mid] < b) lo = mid + 1; else hi = mid; }
            g_kseg[b] = lo;
        }
        // zero-fill slice: 192 blocks grid-stride over the dense attn region,
        // streaming stores (evict-first) keep the 268MB out of L2's way
        size_t start = (size_t)(blockIdx.z * gridDim.x + blockIdx.x) * 256 + t;
        float4* p = (float4*)zero_ptr;
        float4 z4 = make_float4(0.f, 0.f, 0.f, 0.f);
        for (size_t i = start; i < zero_f4; i += (size_t)NZB * 256)
            __stcs(&p[i], z4);
        return;
    }

    int z = blockIdx.z;
    const float* A    = (z == 0) ? A0 : A12;
    const float* W    = (z == 0) ? W0 : ((z == 1) ? W1 : W2);
    const float* bias = (z == 0) ? b0 : ((z == 1) ? b1 : b2);
    float*       C    = (z == 0) ? C0 : ((z == 1) ? C1 : C2);

    int w = t >> 5, lane = t & 31;
    int gid = lane >> 2, tig = lane & 3;
    int m0 = blockIdx.x * 128;
    int n0 = ((int)blockIdx.y - (has_zero ? 1 : 0)) * 64;
    int wm = (w >> 1) * 32;
    int wn = (w & 1) * 32;

    unsigned* sAhi = sm_gemm + SA_HI;
    unsigned* sAlo = sm_gemm + SA_LO;
    unsigned* sWhi = sm_gemm + SW_HI;
    unsigned* sWlo = sm_gemm + SW_LO;

    float acc[2][4][4] = {};

    for (int kk = 0; kk < DIM; kk += 32) {
        __syncthreads();
        // load A tile 128x32 (4 float4/thread), split at store
        #pragma unroll
        for (int i = 0; i < 4; i++) {
            int f = t + i * 256;
            int r = f >> 3, c4 = f & 7;
            float4 av = *(const float4*)&A[(size_t)(m0 + r) * DIM + kk + c4 * 4];
            float vv[4] = {av.x, av.y, av.z, av.w};
            #pragma unroll
            for (int e = 0; e < 4; e++) {
                unsigned hb = f2tf32(vv[e]);
                float hf = __uint_as_float(hb);
                sAhi[r * GP + c4 * 4 + e] = hb;
                sAlo[r * GP + c4 * 4 + e] = f2tf32(vv[e] - hf);
            }
        }
        // load W tile 64x32 (2 float4/thread)
        #pragma unroll
        for (int i = 0; i < 2; i++) {
            int f = t + i * 256;
            int r = f >> 3, c4 = f & 7;
            float4 wv = *(const float4*)&W[(size_t)(n0 + r) * DIM + kk + c4 * 4];
            float vv[4] = {wv.x, wv.y, wv.z, wv.w};
            #pragma unroll
            for (int e = 0; e < 4; e++) {
                unsigned hb = f2tf32(vv[e]);
                float hf = __uint_as_float(hb);
                sWhi[r * GP + c4 * 4 + e] = hb;
                sWlo[r * GP + c4 * 4 + e] = f2tf32(vv[e] - hf);
            }
        }
        __syncthreads();

        #pragma unroll
        for (int ks = 0; ks < 32; ks += 8) {
            unsigned ah[2][4], al[2][4], bh[4][2], bl[4][2];
            #pragma unroll
            for (int i = 0; i < 2; i++) {
                int mr = wm + i * 16 + gid;
                int c  = ks + tig;
                ah[i][0] = sAhi[mr * GP + c];
                ah[i][1] = sAhi[(mr + 8) * GP + c];
                ah[i][2] = sAhi[mr * GP + c + 4];
                ah[i][3] = sAhi[(mr + 8) * GP + c + 4];
                al[i][0] = sAlo[mr * GP + c];
                al[i][1] = sAlo[(mr + 8) * GP + c];
                al[i][2] = sAlo[mr * GP + c + 4];
                al[i][3] = sAlo[(mr + 8) * GP + c + 4];
            }
            #pragma unroll
            for (int j = 0; j < 4; j++) {
                int nr = wn + j * 8 + gid;
                int c  = ks + tig;
                bh[j][0] = sWhi[nr * GP + c];
                bh[j][1] = sWhi[nr * GP + c + 4];
                bl[j][0] = sWlo[nr * GP + c];
                bl[j][1] = sWlo[nr * GP + c + 4];
            }
            #pragma unroll
            for (int i = 0; i < 2; i++)
                #pragma unroll
                for (int j = 0; j < 4; j++) {
                    mma_tf32(acc[i][j], ah[i], bh[j]);
                    mma_tf32(acc[i][j], ah[i], bl[j]);
                    mma_tf32(acc[i][j], al[i], bh[j]);
                }
        }
    }

    #pragma unroll
    for (int i = 0; i < 2; i++) {
        #pragma unroll
        for (int j = 0; j < 4; j++) {
            int n = n0 + wn + j * 8 + tig * 2;
            float bb0 = __ldg(&bias[n]), bb1 = __ldg(&bias[n + 1]);
            int m = m0 + wm + i * 16 + gid;
            *(float2*)&C[(size_t)m * DIM + n] =
                make_float2(acc[i][j][0] + bb0, acc[i][j][1] + bb1);
            *(float2*)&C[(size_t)(m + 8) * DIM + n] =
                make_float2(acc[i][j][2] + bb0, acc[i][j][3] + bb1);
        }
    }
}

// ---------------- tensor-core block-diagonal attention (unchanged) ----------
#define AP 260
#define VP 264
#define PP 36
#define ATTN_SMEM_F (32 * AP * 2 + 32 * VP + 32 * PP + 32)

extern __shared__ float sm_attn[];

__global__ __launch_bounds__(256)
void attn_mma(const float* __restrict__ Q, const float* __restrict__ K,
              const float* __restrict__ V, float* __restrict__ attn,
              float* __restrict__ O, int Mtot) {
    int b  = blockIdx.x;
    int qs = g_qseg[b], qe = g_qseg[b + 1];
    int row0 = qs + blockIdx.y * 32;
    if (row0 >= qe) return;
    int rows = min(32, qe - row0);
    int ks = g_kseg[b], ke = g_kseg[b + 1];
    int nk = ke - ks;

    int t = threadIdx.x;
    int w = t >> 5, lane = t & 31;
    int gid = lane >> 2, tig = lane & 3;

    float* Qs = sm_attn;
    float* Ks = Qs + 32 * AP;
    float* Vs = Ks + 32 * AP;
    float* Ps = Vs + 32 * VP;
    float* rowsum = Ps + 32 * PP;

    if (nk == 0) {
        for (int i = t; i < rows * DIM; i += 256)
            O[(size_t)row0 * DIM + i] = 0.f;
        return;
    }

    for (int i = t; i < 32 * 64; i += 256) {
        int r = i >> 6, c4 = i & 63;
        cp16z(&Qs[r * AP + c4 * 4], &Q[(size_t)(row0 + r) * DIM + c4 * 4], r < rows);
    }
    asm volatile("cp.async.commit_group;\n");
    if (t < 32) rowsum[t] = 0.f;

    int mh  = w & 1;
    int wn0 = (w >> 1) * 8;

    float o_acc[2][4][4] = {};

    int ntiles = (nk + 31) >> 5;
    for (int kt = 0; kt < ntiles; kt++) {
        int kbase = kt << 5;
        __syncthreads();
        for (int i = t; i < 32 * 64; i += 256) {
            int r = i >> 6, c4 = i & 63;
            bool p = kbase + r < nk;
            cp16z(&Ks[r * AP + c4 * 4], &K[(size_t)(ks + kbase + r) * DIM + c4 * 4], p);
            cp16z(&Vs[r * VP + c4 * 4], &V[(size_t)(ks + kbase + r) * DIM + c4 * 4], p);
        }
        asm volatile("cp.async.commit_group;\n");
        asm volatile("cp.async.wait_group 0;\n");
        __syncthreads();

        float sacc[4] = {0.f, 0.f, 0.f, 0.f};
        #pragma unroll
        for (int kk = 0; kk < DIM; kk += 8) {
            unsigned ah[4], al[4], bh[2], bl[2];
            int c = kk + tig;
            int mr = mh * 16 + gid;
            split_tf32(Qs[mr * AP + c],           ah[0], al[0]);
            split_tf32(Qs[(mr + 8) * AP + c],     ah[1], al[1]);
            split_tf32(Qs[mr * AP + c + 4],       ah[2], al[2]);
            split_tf32(Qs[(mr + 8) * AP + c + 4], ah[3], al[3]);
            int nr = wn0 + gid;
            split_tf32(Ks[nr * AP + c],     bh[0], bl[0]);
            split_tf32(Ks[nr * AP + c + 4], bh[1], bl[1]);
            mma_tf32(sacc, ah, bh);
            mma_tf32(sacc, ah, bl);
            mma_tf32(sacc, al, bh);
        }
        int kn = kbase + wn0 + 2 * tig;
        float e0 = (kn     < nk) ? __expf(sacc[0] * SCALE) : 0.f;
        float e1 = (kn + 1 < nk) ? __expf(sacc[1] * SCALE) : 0.f;
        float e2 = (kn     < nk) ? __expf(sacc[2] * SCALE) : 0.f;
        float e3 = (kn + 1 < nk) ? __expf(sacc[3] * SCALE) : 0.f;
        int pr = mh * 16 + gid;
        Ps[pr * PP + wn0 + 2 * tig]           = e0;
        Ps[pr * PP + wn0 + 2 * tig + 1]       = e1;
        Ps[(pr + 8) * PP + wn0 + 2 * tig]     = e2;
        Ps[(pr + 8) * PP + wn0 + 2 * tig + 1] = e3;
        __syncthreads();

        #pragma unroll
        for (int i = 0; i < 4; i++) {
            int r = w + i * 8;
            float e = Ps[r * PP + lane];
            float s = e;
            #pragma unroll
            for (int off = 16; off; off >>= 1) s += __shfl_xor_sync(0xFFFFFFFFu, s, off);
            if (lane == 0) rowsum[r] += s;
            if (r < rows && kbase + lane < nk)
                attn[(size_t)(row0 + r) * Mtot + ks + kbase + lane] = e;
        }

        #pragma unroll
        for (int kk = 0; kk < 32; kk += 8) {
            unsigned pah[2][4], pal[2][4];
            int c = kk + tig;
            #pragma unroll
            for (int i = 0; i < 2; i++) {
                int mr = i * 16 + gid;
                split_tf32(Ps[mr * PP + c],           pah[i][0], pal[i][0]);
                split_tf32(Ps[(mr + 8) * PP + c],     pah[i][1], pal[i][1]);
                split_tf32(Ps[mr * PP + c + 4],       pah[i][2], pal[i][2]);
                split_tf32(Ps[(mr + 8) * PP + c + 4], pah[i][3], pal[i][3]);
            }
            #pragma unroll
            for (int j = 0; j < 4; j++) {
                int n = w * 32 + 8 * j + gid;
                unsigned vbh[2], vbl[2];
                split_tf32(Vs[c * VP + n],       vbh[0], vbl[0]);
                split_tf32(Vs[(c + 4) * VP + n], vbh[1], vbl[1]);
                #pragma unroll
                for (int i = 0; i < 2; i++) {
                    mma_tf32(o_acc[i][j], pah[i], vbh);
                    mma_tf32(o_acc[i][j], pah[i], vbl);
                    mma_tf32(o_acc[i][j], pal[i], vbh);
                }
            }
        }
    }
    __syncthreads();
    if (t < 32) rowsum[t] = (rowsum[t] > 0.f) ? (1.f / rowsum[t]) : 0.f;
    __syncthreads();

    #pragma unroll
    for (int i = 0; i < 4; i++) {
        int r = w + i * 8;
        if (r < rows) {
            float inv = rowsum[r];
            size_t base = (size_t)(row0 + r) * Mtot + ks;
            for (int j = lane; j < nk; j += 32) attn[base + j] *= inv;
        }
    }
    #pragma unroll
    for (int i = 0; i < 2; i++) {
        int r = i * 16 + gid;
        if (r < rows) {
            float inv = rowsum[r];
            #pragma unroll
            for (int j = 0; j < 4; j++) {
                int n = w * 32 + 8 * j + 2 * tig;
                *(float2*)&O[(size_t)(row0 + r) * DIM + n] =
                    make_float2(o_acc[i][j][0] * inv, o_acc[i][j][1] * inv);
            }
        }
        int r8 = r + 8;
        if (r8 < rows) {
            float inv = rowsum[r8];
            #pragma unroll
            for (int j = 0; j < 4; j++) {
                int n = w * 32 + 8 * j + 2 * tig;
                *(float2*)&O[(size_t)(row0 + r8) * DIM + n] =
                    make_float2(o_acc[i][j][2] * inv, o_acc[i][j][3] * inv);
            }
        }
    }
}

// ---------------- launch (single stream, no events) -------------------------
extern "C" void kernel_launch(void* const* d_in, const int* in_sizes, int n_in,
                              void* d_out, int out_size) {
    const float* q_feat = (const float*)d_in[0];
    const float* k_feat = (const float*)d_in[1];
    const int*   q_batch = (const int*)d_in[2];
    const int*   k_batch = (const int*)d_in[3];
    const float* Wq = (const float*)d_in[4];
    const float* bq = (const float*)d_in[5];
    const float* Wk = (const float*)d_in[6];
    const float* bk = (const float*)d_in[7];
    const float* Wv = (const float*)d_in[8];
    const float* bv = (const float*)d_in[9];
    const float* Wo = (const float*)d_in[10];
    const float* bo = (const float*)d_in[11];

    int n = in_sizes[0] / DIM;
    int m = in_sizes[1] / DIM;

    float* out      = (float*)d_out;
    float* attended = out;                        // [n, DIM]
    float* attn     = out + (size_t)n * DIM;      // [n, m]

    float *Qd, *Kd, *Vd, *Od;
    cudaGetSymbolAddress((void**)&Qd, g_Q);
    cudaGetSymbolAddress((void**)&Kd, g_K);
    cudaGetSymbolAddress((void**)&Vd, g_V);
    cudaGetSymbolAddress((void**)&Od, g_O);

    const size_t attn_smem = ATTN_SMEM_F * sizeof(float);
    const size_t gemm_smem = GEMM_SMEM_U32 * sizeof(unsigned);
    cudaFuncSetAttribute(attn_mma, cudaFuncAttributeMaxDynamicSharedMemorySize,
                         (int)attn_smem);
    cudaFuncSetAttribute(gemm3_tf32, cudaFuncAttributeMaxDynamicSharedMemorySize,
                         (int)gemm_smem);

    size_t attn_f4 = (size_t)n * m / 4;

    // 1. fused QKV projection + attn zero-fill + segment boundaries
    gemm3_tf32<<<dim3(n / 128, 5, 3), 256, gemm_smem>>>(
        q_feat, k_feat, Wq, bq, Wk, bk, Wv, bv, Qd, Kd, Vd,
        attn, attn_f4, q_batch, k_batch, n, m);
    // 2. tensor-core block-diagonal attention
    attn_mma<<<dim3(NB, 32), 256, attn_smem>>>(Qd, Kd, Vd, attn, Od, m);
    // 3. output projection (no zero slice)
    gemm3_tf32<<<dim3(n / 128, 4, 1), 256, gemm_smem>>>(
        Od, Od, Wo, bo, Wo, bo, Wo, bo, attended, attended, attended,
        nullptr, 0, nullptr, nullptr, 0, 0);
}

// round 11
// speedup vs baseline: 1.3770x; 1.1719x over previous
#include <cuda_runtime.h>
#include <cstdint>

#define NQMAX 8192
#define DIM   256
#define NB    64
#define SCALE 0.0625f   /* 1/sqrt(256) exactly */

// ---------------- scratch (device globals: allocation-free) ----------------
__device__ float g_Q[NQMAX * DIM];
__device__ float g_K[NQMAX * DIM];
__device__ float g_V[NQMAX * DIM];
__device__ float g_O[NQMAX * DIM];
__device__ int   g_qseg[NB + 1];
__device__ int   g_kseg[NB + 1];

// ---------------- tf32 / mma helpers ---------------------------------------
__device__ __forceinline__ unsigned f2tf32(float x) {
    unsigned r;
    asm("cvt.rna.tf32.f32 %0, %1;" : "=r"(r) : "f"(x));
    return r;
}
__device__ __forceinline__ void split_tf32(float x, unsigned& hi, unsigned& lo) {
    hi = f2tf32(x);
    lo = f2tf32(x - __uint_as_float(hi));
}
__device__ __forceinline__ void mma_tf32(float* d, const unsigned* a, const unsigned* b) {
    asm volatile(
        "mma.sync.aligned.m16n8k8.row.col.f32.tf32.tf32.f32 "
        "{%0,%1,%2,%3}, {%4,%5,%6,%7}, {%8,%9}, {%0,%1,%2,%3};\n"
        : "+f"(d[0]), "+f"(d[1]), "+f"(d[2]), "+f"(d[3])
        : "r"(a[0]), "r"(a[1]), "r"(a[2]), "r"(a[3]), "r"(b[0]), "r"(b[1]));
}
__device__ __forceinline__ void cp16z(void* s, const void* g, bool p) {
    unsigned sa = (unsigned)__cvta_generic_to_shared(s);
    int sz = p ? 16 : 0;
    asm volatile("cp.async.cg.shared.global [%0], [%1], 16, %2;\n"
                 :: "r"(sa), "l"(g), "r"(sz));
}

// ---------------- GEMM: C[Mr,256] = A[Mr,256] @ W[256,256]^T + bias --------
// 2xTF32: A hi-only, W split hi/lo -> acc += A_hi*(W_hi + W_lo).
// Dropped term (A_lo*W_hi) error ~1.4e-4 rel (incoherent over K), far under
// the 1e-3 gate. Cuts MMA 96->64, LDS 128->96, A-conversion ALU/STS in half
// per chunk vs 3xTF32. smem 37KB. pitch 36: frag bank = 4r+c, conflict-free.
#define GP 36
#define SA_HI 0
#define SW_HI (128 * GP)
#define SW_LO (128 * GP + 64 * GP)
#define GEMM_SMEM_U32 (128 * GP + 2 * 64 * GP)
#define NZB  192

extern __shared__ unsigned sm_gemm[];

__global__ __launch_bounds__(256, 3)
void gemm3_tf32(const float* __restrict__ A0, const float* __restrict__ A12,
                const float* __restrict__ W0, const float* __restrict__ b0,
                const float* __restrict__ W1, const float* __restrict__ b1,
                const float* __restrict__ W2, const float* __restrict__ b2,
                float* __restrict__ C0, float* __restrict__ C1, float* __restrict__ C2,
                float* __restrict__ zero_ptr, size_t zero_f4,
                const int* __restrict__ qb, const int* __restrict__ kb,
                int nq, int mk) {
    int t = threadIdx.x;
    bool has_zero = (zero_ptr != nullptr);

    if (has_zero && blockIdx.y == 0) {
        // one block also computes segment boundaries for the attn kernel
        if (blockIdx.x == 0 && blockIdx.z == 0 && t <= NB) {
            int b = t;
            int lo = 0, hi = nq;
            while (lo < hi) { int mid = (lo + hi) >> 1; if (qb[mid] < b) lo = mid + 1; else hi = mid; }
            g_qseg[b] = lo;
            lo = 0; hi = mk;
            while (lo < hi) { int mid = (lo + hi) >> 1; if (kb[mid] < b) lo = mid + 1; else hi = mid; }
            g_kseg[b] = lo;
        }
        // zero-fill slice: 192 blocks grid-stride over the dense attn region
        size_t start = (size_t)(blockIdx.z * gridDim.x + blockIdx.x) * 256 + t;
        float4* p = (float4*)zero_ptr;
        float4 z4 = make_float4(0.f, 0.f, 0.f, 0.f);
        for (size_t i = start; i < zero_f4; i += (size_t)NZB * 256)
            __stcs(&p[i], z4);
        return;
    }

    int z = blockIdx.z;
    const float* A    = (z == 0) ? A0 : A12;
    const float* W    = (z == 0) ? W0 : ((z == 1) ? W1 : W2);
    const float* bias = (z == 0) ? b0 : ((z == 1) ? b1 : b2);
    float*       C    = (z == 0) ? C0 : ((z == 1) ? C1 : C2);

    int w = t >> 5, lane = t & 31;
    int gid = lane >> 2, tig = lane & 3;
    int m0 = blockIdx.x * 128;
    int n0 = ((int)blockIdx.y - (has_zero ? 1 : 0)) * 64;
    int wm = (w >> 1) * 32;
    int wn = (w & 1) * 32;

    unsigned* sAhi = sm_gemm + SA_HI;
    unsigned* sWhi = sm_gemm + SW_HI;
    unsigned* sWlo = sm_gemm + SW_LO;

    float acc[2][4][4] = {};

    for (int kk = 0; kk < DIM; kk += 32) {
        __syncthreads();
        // load A tile 128x32 (4 float4/thread), hi-only conversion
        #pragma unroll
        for (int i = 0; i < 4; i++) {
            int f = t + i * 256;
            int r = f >> 3, c4 = f & 7;
            float4 av = *(const float4*)&A[(size_t)(m0 + r) * DIM + kk + c4 * 4];
            sAhi[r * GP + c4 * 4 + 0] = f2tf32(av.x);
            sAhi[r * GP + c4 * 4 + 1] = f2tf32(av.y);
            sAhi[r * GP + c4 * 4 + 2] = f2tf32(av.z);
            sAhi[r * GP + c4 * 4 + 3] = f2tf32(av.w);
        }
        // load W tile 64x32 (2 float4/thread), split hi/lo at store
        #pragma unroll
        for (int i = 0; i < 2; i++) {
            int f = t + i * 256;
            int r = f >> 3, c4 = f & 7;
            float4 wv = *(const float4*)&W[(size_t)(n0 + r) * DIM + kk + c4 * 4];
            float vv[4] = {wv.x, wv.y, wv.z, wv.w};
            #pragma unroll
            for (int e = 0; e < 4; e++) {
                unsigned hb = f2tf32(vv[e]);
                float hf = __uint_as_float(hb);
                sWhi[r * GP + c4 * 4 + e] = hb;
                sWlo[r * GP + c4 * 4 + e] = f2tf32(vv[e] - hf);
            }
        }
        __syncthreads();

        #pragma unroll
        for (int ks = 0; ks < 32; ks += 8) {
            unsigned ah[2][4], bh[4][2], bl[4][2];
            #pragma unroll
            for (int i = 0; i < 2; i++) {
                int mr = wm + i * 16 + gid;
                int c  = ks + tig;
                ah[i][0] = sAhi[mr * GP + c];
                ah[i][1] = sAhi[(mr + 8) * GP + c];
                ah[i][2] = sAhi[mr * GP + c + 4];
                ah[i][3] = sAhi[(mr + 8) * GP + c + 4];
            }
            #pragma unroll
            for (int j = 0; j < 4; j++) {
                int nr = wn + j * 8 + gid;
                int c  = ks + tig;
                bh[j][0] = sWhi[nr * GP + c];
                bh[j][1] = sWhi[nr * GP + c + 4];
                bl[j][0] = sWlo[nr * GP + c];
                bl[j][1] = sWlo[nr * GP + c + 4];
            }
            #pragma unroll
            for (int i = 0; i < 2; i++)
                #pragma unroll
                for (int j = 0; j < 4; j++) {
                    mma_tf32(acc[i][j], ah[i], bh[j]);
                    mma_tf32(acc[i][j], ah[i], bl[j]);
                }
        }
    }

    #pragma unroll
    for (int i = 0; i < 2; i++) {
        #pragma unroll
        for (int j = 0; j < 4; j++) {
            int n = n0 + wn + j * 8 + tig * 2;
            float bb0 = __ldg(&bias[n]), bb1 = __ldg(&bias[n + 1]);
            int m = m0 + wm + i * 16 + gid;
            *(float2*)&C[(size_t)m * DIM + n] =
                make_float2(acc[i][j][0] + bb0, acc[i][j][1] + bb1);
            *(float2*)&C[(size_t)(m + 8) * DIM + n] =
                make_float2(acc[i][j][2] + bb0, acc[i][j][3] + bb1);
        }
    }
}

// ---------------- tensor-core block-diagonal attention ----------------------
// 2xTF32: QK = Q_hi*(K_hi+K_lo); PV = P_hi*(V_hi+V_lo). Same error budget.
#define AP 260
#define VP 264
#define PP 36
#define ATTN_SMEM_F (32 * AP * 2 + 32 * VP + 32 * PP + 32)

extern __shared__ float sm_attn[];

__global__ __launch_bounds__(256)
void attn_mma(const float* __restrict__ Q, const float* __restrict__ K,
              const float* __restrict__ V, float* __restrict__ attn,
              float* __restrict__ O, int Mtot) {
    int b  = blockIdx.x;
    int qs = g_qseg[b], qe = g_qseg[b + 1];
    int row0 = qs + blockIdx.y * 32;
    if (row0 >= qe) return;
    int rows = min(32, qe - row0);
    int ks = g_kseg[b], ke = g_kseg[b + 1];
    int nk = ke - ks;

    int t = threadIdx.x;
    int w = t >> 5, lane = t & 31;
    int gid = lane >> 2, tig = lane & 3;

    float* Qs = sm_attn;
    float* Ks = Qs + 32 * AP;
    float* Vs = Ks + 32 * AP;
    float* Ps = Vs + 32 * VP;
    float* rowsum = Ps + 32 * PP;

    if (nk == 0) {
        for (int i = t; i < rows * DIM; i += 256)
            O[(size_t)row0 * DIM + i] = 0.f;
        return;
    }

    for (int i = t; i < 32 * 64; i += 256) {
        int r = i >> 6, c4 = i & 63;
        cp16z(&Qs[r * AP + c4 * 4], &Q[(size_t)(row0 + r) * DIM + c4 * 4], r < rows);
    }
    asm volatile("cp.async.commit_group;\n");
    if (t < 32) rowsum[t] = 0.f;

    int mh  = w & 1;
    int wn0 = (w >> 1) * 8;

    float o_acc[2][4][4] = {};

    int ntiles = (nk + 31) >> 5;
    for (int kt = 0; kt < ntiles; kt++) {
        int kbase = kt << 5;
        __syncthreads();
        for (int i = t; i < 32 * 64; i += 256) {
            int r = i >> 6, c4 = i & 63;
            bool p = kbase + r < nk;
            cp16z(&Ks[r * AP + c4 * 4], &K[(size_t)(ks + kbase + r) * DIM + c4 * 4], p);
            cp16z(&Vs[r * VP + c4 * 4], &V[(size_t)(ks + kbase + r) * DIM + c4 * 4], p);
        }
        asm volatile("cp.async.commit_group;\n");
        asm volatile("cp.async.wait_group 0;\n");
        __syncthreads();

        // ---- QK^T, 2-pass: Q hi-only, K split ----
        float sacc[4] = {0.f, 0.f, 0.f, 0.f};
        #pragma unroll
        for (int kk = 0; kk < DIM; kk += 8) {
            unsigned ah[4], bh[2], bl[2];
            int c = kk + tig;
            int mr = mh * 16 + gid;
            ah[0] = f2tf32(Qs[mr * AP + c]);
            ah[1] = f2tf32(Qs[(mr + 8) * AP + c]);
            ah[2] = f2tf32(Qs[mr * AP + c + 4]);
            ah[3] = f2tf32(Qs[(mr + 8) * AP + c + 4]);
            int nr = wn0 + gid;
            split_tf32(Ks[nr * AP + c],     bh[0], bl[0]);
            split_tf32(Ks[nr * AP + c + 4], bh[1], bl[1]);
            mma_tf32(sacc, ah, bh);
            mma_tf32(sacc, ah, bl);
        }
        int kn = kbase + wn0 + 2 * tig;
        float e0 = (kn     < nk) ? __expf(sacc[0] * SCALE) : 0.f;
        float e1 = (kn + 1 < nk) ? __expf(sacc[1] * SCALE) : 0.f;
        float e2 = (kn     < nk) ? __expf(sacc[2] * SCALE) : 0.f;
        float e3 = (kn + 1 < nk) ? __expf(sacc[3] * SCALE) : 0.f;
        int pr = mh * 16 + gid;
        Ps[pr * PP + wn0 + 2 * tig]           = e0;
        Ps[pr * PP + wn0 + 2 * tig + 1]       = e1;
        Ps[(pr + 8) * PP + wn0 + 2 * tig]     = e2;
        Ps[(pr + 8) * PP + wn0 + 2 * tig + 1] = e3;
        __syncthreads();

        #pragma unroll
        for (int i = 0; i < 4; i++) {
            int r = w + i * 8;
            float e = Ps[r * PP + lane];
            float s = e;
            #pragma unroll
            for (int off = 16; off; off >>= 1) s += __shfl_xor_sync(0xFFFFFFFFu, s, off);
            if (lane == 0) rowsum[r] += s;
            if (r < rows && kbase + lane < nk)
                attn[(size_t)(row0 + r) * Mtot + ks + kbase + lane] = e;
        }

        // ---- PV, 2-pass: P hi-only, V split ----
        #pragma unroll
        for (int kk = 0; kk < 32; kk += 8) {
            unsigned pah[2][4];
            int c = kk + tig;
            #pragma unroll
            for (int i = 0; i < 2; i++) {
                int mr = i * 16 + gid;
                pah[i][0] = f2tf32(Ps[mr * PP + c]);
                pah[i][1] = f2tf32(Ps[(mr + 8) * PP + c]);
                pah[i][2] = f2tf32(Ps[mr * PP + c + 4]);
                pah[i][3] = f2tf32(Ps[(mr + 8) * PP + c + 4]);
            }
            #pragma unroll
            for (int j = 0; j < 4; j++) {
                int n = w * 32 + 8 * j + gid;
                unsigned vbh[2], vbl[2];
                split_tf32(Vs[c * VP + n],       vbh[0], vbl[0]);
                split_tf32(Vs[(c + 4) * VP + n], vbh[1], vbl[1]);
                #pragma unroll
                for (int i = 0; i < 2; i++) {
                    mma_tf32(o_acc[i][j], pah[i], vbh);
                    mma_tf32(o_acc[i][j], pah[i], vbl);
                }
            }
        }
    }
    __syncthreads();
    if (t < 32) rowsum[t] = (rowsum[t] > 0.f) ? (1.f / rowsum[t]) : 0.f;
    __syncthreads();

    #pragma unroll
    for (int i = 0; i < 4; i++) {
        int r = w + i * 8;
        if (r < rows) {
            float inv = rowsum[r];
            size_t base = (size_t)(row0 + r) * Mtot + ks;
            for (int j = lane; j < nk; j += 32) attn[base + j] *= inv;
        }
    }
    #pragma unroll
    for (int i = 0; i < 2; i++) {
        int r = i * 16 + gid;
        if (r < rows) {
            float inv = rowsum[r];
            #pragma unroll
            for (int j = 0; j < 4; j++) {
                int n = w * 32 + 8 * j + 2 * tig;
                *(float2*)&O[(size_t)(row0 + r) * DIM + n] =
                    make_float2(o_acc[i][j][0] * inv, o_acc[i][j][1] * inv);
            }
        }
        int r8 = r + 8;
        if (r8 < rows) {
            float inv = rowsum[r8];
            #pragma unroll
            for (int j = 0; j < 4; j++) {
                int n = w * 32 + 8 * j + 2 * tig;
                *(float2*)&O[(size_t)(row0 + r8) * DIM + n] =
                    make_float2(o_acc[i][j][2] * inv, o_acc[i][j][3] * inv);
            }
        }
    }
}

// ---------------- launch (single stream, no events) -------------------------
extern "C" void kernel_launch(void* const* d_in, const int* in_sizes, int n_in,
                              void* d_out, int out_size) {
    const float* q_feat = (const float*)d_in[0];
    const float* k_feat = (const float*)d_in[1];
    const int*   q_batch = (const int*)d_in[2];
    const int*   k_batch = (const int*)d_in[3];
    const float* Wq = (const float*)d_in[4];
    const float* bq = (const float*)d_in[5];
    const float* Wk = (const float*)d_in[6];
    const float* bk = (const float*)d_in[7];
    const float* Wv = (const float*)d_in[8];
    const float* bv = (const float*)d_in[9];
    const float* Wo = (const float*)d_in[10];
    const float* bo = (const float*)d_in[11];

    int n = in_sizes[0] / DIM;
    int m = in_sizes[1] / DIM;

    float* out      = (float*)d_out;
    float* attended = out;                        // [n, DIM]
    float* attn     = out + (size_t)n * DIM;      // [n, m]

    float *Qd, *Kd, *Vd, *Od;
    cudaGetSymbolAddress((void**)&Qd, g_Q);
    cudaGetSymbolAddress((void**)&Kd, g_K);
    cudaGetSymbolAddress((void**)&Vd, g_V);
    cudaGetSymbolAddress((void**)&Od, g_O);

    const size_t attn_smem = ATTN_SMEM_F * sizeof(float);
    const size_t gemm_smem = GEMM_SMEM_U32 * sizeof(unsigned);
    cudaFuncSetAttribute(attn_mma, cudaFuncAttributeMaxDynamicSharedMemorySize,
                         (int)attn_smem);
    cudaFuncSetAttribute(gemm3_tf32, cudaFuncAttributeMaxDynamicSharedMemorySize,
                         (int)gemm_smem);

    size_t attn_f4 = (size_t)n * m / 4;

    // 1. fused QKV projection + attn zero-fill + segment boundaries
    gemm3_tf32<<<dim3(n / 128, 5, 3), 256, gemm_smem>>>(
        q_feat, k_feat, Wq, bq, Wk, bk, Wv, bv, Qd, Kd, Vd,
        attn, attn_f4, q_batch, k_batch, n, m);
    // 2. tensor-core block-diagonal attention
    attn_mma<<<dim3(NB, 32), 256, attn_smem>>>(Qd, Kd, Vd, attn, Od, m);
    // 3. output projection (no zero slice)
    gemm3_tf32<<<dim3(n / 128, 4, 1), 256, gemm_smem>>>(
        Od, Od, Wo, bo, Wo, bo, Wo, bo, attended, attended, attended,
        nullptr, 0, nullptr, nullptr, 0, 0);
}